// round 2
// baseline (speedup 1.0000x reference)
#include <cuda_runtime.h>
#include <cstdint>

// ---------------------------------------------------------------------------
// MLPDecoder (NRI-style) — fp32 baseline with algebraic layer-1 factorization
//
// Shapes: B=4, A=32, T=64, D=64, S=4, E=4 (experts 1..3 active), R=992
//   MH=MO=NH=256.  Nodes N = B*T*A = 8192. Edges per (b,t): 992 (rec-major).
//
// Pipeline:
//   k1x : inputs[B,A,T,D] -> Xn[node=(b,t,a)][64]
//   k1g : gates G[e][bt*992+r] = sum_s rel_type[b,r,s,e+1]*state[b,send,t,s]
//   k2  : P,Q node GEMMs:  PQ[e*2+half][node][256] = Xn @ W1 halves (+b1 on P)
//   k3  : edge GEMM (the 100-GFLOP workhorse):
//           h1 = lrelu(P[send]+Q[rec]); h2 = lrelu(h1@W2 + b2); agg += h2*g
//         block = one (b,t) x 4 receivers (128 rows incl. 1 dummy/receiver),
//         FFMA2-packed over row pairs, agg reduced in registers.
//   k5  : output MLP (aug=[x|agg] -> 256 -> 256 -> 64), +x, write [B,A,63,D]
// ---------------------------------------------------------------------------

#define NNODE   8192
#define NEDGE   253952       // 256*992
#define NBT     256

// Scratch (static device globals; allocation-free)
__device__ float d_X  [NNODE * 64];
__device__ float d_PQ [6 * NNODE * 256];     // [e*2+half][node][256]
__device__ float d_G  [3 * NEDGE];
__device__ float d_AGG[NNODE * 256];

__device__ __forceinline__ float lrelu(float v) {
    return fmaxf(v, 0.01f * v);
}
__device__ __forceinline__ unsigned long long dup2(float w) {
    unsigned long long r;
    unsigned int u = __float_as_uint(w);
    asm("mov.b64 %0, {%1, %1};" : "=l"(r) : "r"(u));
    return r;
}
__device__ __forceinline__ void ffma2(unsigned long long& d,
                                      unsigned long long a,
                                      unsigned long long b) {
    asm("fma.rn.f32x2 %0, %1, %2, %0;" : "+l"(d) : "l"(a), "l"(b));
}
__device__ __forceinline__ float lo32(unsigned long long v) {
    return __uint_as_float((unsigned int)(v & 0xffffffffull));
}
__device__ __forceinline__ float hi32(unsigned long long v) {
    return __uint_as_float((unsigned int)(v >> 32));
}

// ------------------------- k1x: node-layout transpose ----------------------
__global__ void k1x(const float4* __restrict__ inputs4) {
    int idx = blockIdx.x * blockDim.x + threadIdx.x;       // < 131072
    if (idx >= NNODE * 16) return;
    int n = idx >> 4, q = idx & 15;
    int b = n >> 11, t = (n >> 5) & 63, a = n & 31;
    ((float4*)d_X)[idx] = inputs4[(((b * 32 + a) * 64) + t) * 16 + q];
}

// ------------------------- k1g: edge gates ---------------------------------
__global__ void k1g(const float* __restrict__ state,
                    const float4* __restrict__ rel_type4) {
    int idx = blockIdx.x * blockDim.x + threadIdx.x;       // < 253952
    if (idx >= NEDGE) return;
    int bt = idx / 992, r = idx - bt * 992;
    int b = bt >> 6, t = bt & 63;
    int rec = r / 31, j = r - rec * 31;
    int send = j + (j >= rec);
    const float4 st = *(const float4*)&state[(((b * 32 + send) * 64) + t) * 4];
    // rel_type[b][r][s][e] : 16 floats = 4 float4 (one per s)
    const float4* rt = rel_type4 + (b * 992 + r) * 4;
    float4 r0 = rt[0], r1 = rt[1], r2 = rt[2], r3 = rt[3];
    // e index in float4: .y = e1, .z = e2, .w = e3
    d_G[0 * NEDGE + idx] = st.x * r0.y + st.y * r1.y + st.z * r2.y + st.w * r3.y;
    d_G[1 * NEDGE + idx] = st.x * r0.z + st.y * r1.z + st.z * r2.z + st.w * r3.z;
    d_G[2 * NEDGE + idx] = st.x * r0.w + st.y * r1.w + st.z * r2.w + st.w * r3.w;
}

// ------------------------- k2: P/Q node GEMMs ------------------------------
// grid 256 blocks x 256 threads; each block: 32 node rows, all 6 (e,half).
__global__ __launch_bounds__(256) void k2(const float* __restrict__ w1,
                                          const float* __restrict__ b1) {
    __shared__ float xs[32][64];
    int row0 = blockIdx.x * 32;
    int tid = threadIdx.x;
    for (int i = tid; i < 32 * 64; i += 256)
        xs[i >> 6][i & 63] = d_X[row0 * 64 + i];
    __syncthreads();

    for (int chunk = 0; chunk < 6; ++chunk) {
        int e = chunk >> 1, half = chunk & 1;
        const float* W = w1 + ((size_t)((e + 1) * 128 + half * 64)) * 256;
        float acc[32];
#pragma unroll
        for (int m = 0; m < 32; ++m) acc[m] = 0.f;
#pragma unroll 4
        for (int k = 0; k < 64; ++k) {
            float w = W[k * 256 + tid];
#pragma unroll
            for (int m = 0; m < 32; ++m) acc[m] += xs[m][k] * w;
        }
        float bias = (half == 0) ? b1[(e + 1) * 256 + tid] : 0.f;
        float* dst = d_PQ + ((size_t)chunk * NNODE + row0) * 256 + tid;
#pragma unroll
        for (int m = 0; m < 32; ++m) dst[m * 256] = acc[m] + bias;
    }
}

// ------------------------- k3: edge GEMM + gated aggregation ---------------
// grid 2048 blocks (bt*8 + receiver-quad), 256 threads.
// smem: h1T[256][130] (transposed, padded) + g_s[128]
#define K3_SMEM (256 * 130 * 4 + 128 * 4)

__global__ __launch_bounds__(256, 1) void k3(const float* __restrict__ w2,
                                             const float* __restrict__ b2) {
    extern __shared__ float smem[];
    float* h1T = smem;                 // [k][m], stride 130
    float* g_s = smem + 256 * 130;     // [128]

    int tid = threadIdx.x;
    int bt = blockIdx.x >> 3;
    int a0 = (blockIdx.x & 7) << 2;
    int cg = tid & 63, rg = tid >> 6;
    int c0 = cg * 4;

    float aggv0 = 0.f, aggv1 = 0.f, aggv2 = 0.f, aggv3 = 0.f;

    for (int e = 0; e < 3; ++e) {
        // ---- build h1T (thread tid = feature k) ----
        {
            const float* Pb = d_PQ + ((size_t)(e * 2) * NNODE + bt * 32) * 256 + tid;
            const float* Qb = d_PQ + ((size_t)(e * 2 + 1) * NNODE + bt * 32) * 256 + tid;
            float* hrow = h1T + tid * 130;
#pragma unroll
            for (int grp = 0; grp < 4; ++grp) {
                int rec = a0 + grp;
                float q = Qb[rec * 256];
#pragma unroll 31
                for (int j = 0; j < 31; ++j) {
                    int send = j + (j >= rec);
                    float v = Pb[send * 256] + q;
                    hrow[grp * 32 + j] = lrelu(v);
                }
                hrow[grp * 32 + 31] = 0.f;   // dummy row
            }
        }
        if (tid < 128) {
            int grp = tid >> 5, j = tid & 31;
            g_s[tid] = (j < 31)
                ? d_G[e * NEDGE + bt * 992 + (a0 + grp) * 31 + j] : 0.f;
        }
        __syncthreads();

        // ---- GEMM: 128 rows x 256 cols x 256 K, FFMA2 over row pairs ----
        unsigned long long acc2[16][4];
#pragma unroll
        for (int p = 0; p < 16; ++p)
#pragma unroll
            for (int c = 0; c < 4; ++c) acc2[p][c] = 0ull;

        const float* W = w2 + (size_t)(e + 1) * 65536 + c0;   // row stride 256
        const float* hbase = h1T + rg * 32;

        float4 wv = *(const float4*)W;
#pragma unroll 2
        for (int k = 0; k < 256; ++k) {
            int kn = (k < 255) ? k + 1 : 255;
            float4 wnext = *(const float4*)(W + kn * 256);
            unsigned long long wd0 = dup2(wv.x), wd1 = dup2(wv.y);
            unsigned long long wd2 = dup2(wv.z), wd3 = dup2(wv.w);
            const unsigned long long* hp =
                (const unsigned long long*)(hbase + k * 130);
#pragma unroll
            for (int p = 0; p < 16; ++p) {
                unsigned long long h2 = hp[p];
                ffma2(acc2[p][0], h2, wd0);
                ffma2(acc2[p][1], h2, wd1);
                ffma2(acc2[p][2], h2, wd2);
                ffma2(acc2[p][3], h2, wd3);
            }
            wv = wnext;
        }

        // ---- epilogue: lrelu(+b2), gate, reduce rows ----
        float4 b2v = *(const float4*)(b2 + (e + 1) * 256 + c0);
        float bc0 = b2v.x, bc1 = b2v.y, bc2 = b2v.z, bc3 = b2v.w;
#pragma unroll
        for (int p = 0; p < 16; ++p) {
            float glo = g_s[rg * 32 + 2 * p];
            float ghi = g_s[rg * 32 + 2 * p + 1];
            aggv0 += lrelu(lo32(acc2[p][0]) + bc0) * glo
                   + lrelu(hi32(acc2[p][0]) + bc0) * ghi;
            aggv1 += lrelu(lo32(acc2[p][1]) + bc1) * glo
                   + lrelu(hi32(acc2[p][1]) + bc1) * ghi;
            aggv2 += lrelu(lo32(acc2[p][2]) + bc2) * glo
                   + lrelu(hi32(acc2[p][2]) + bc2) * ghi;
            aggv3 += lrelu(lo32(acc2[p][3]) + bc3) * glo
                   + lrelu(hi32(acc2[p][3]) + bc3) * ghi;
        }
        __syncthreads();   // before next expert overwrites h1T / g_s
    }

    int node = bt * 32 + a0 + rg;
    float4 o; o.x = aggv0; o.y = aggv1; o.z = aggv2; o.w = aggv3;
    *(float4*)(d_AGG + (size_t)node * 256 + c0) = o;
}

// ------------------------- k5: output MLP + residual + write ---------------
// grid 512 blocks x 256 threads; 16 node rows per block.
__global__ __launch_bounds__(256) void k5(const float* __restrict__ fw1,
                                          const float* __restrict__ fb1,
                                          const float* __restrict__ fw2,
                                          const float* __restrict__ fb2,
                                          const float* __restrict__ fw3,
                                          const float* __restrict__ fb3,
                                          float* __restrict__ out) {
    __shared__ float aug[16][320];     // also reused as h2 buffer
    __shared__ float hbuf[16][256];
    int row0 = blockIdx.x * 16;
    int tid = threadIdx.x;

    for (int i = tid; i < 16 * 64; i += 256)
        aug[i >> 6][i & 63] = d_X[row0 * 64 + i];
    for (int i = tid; i < 16 * 256; i += 256)
        aug[i >> 8][64 + (i & 255)] = d_AGG[(size_t)row0 * 256 + i];
    __syncthreads();

    // layer 1: 320 -> 256
    {
        float acc[16];
#pragma unroll
        for (int m = 0; m < 16; ++m) acc[m] = 0.f;
#pragma unroll 4
        for (int k = 0; k < 320; ++k) {
            float w = fw1[k * 256 + tid];
#pragma unroll
            for (int m = 0; m < 16; ++m) acc[m] += aug[m][k] * w;
        }
        float b = fb1[tid];
#pragma unroll
        for (int m = 0; m < 16; ++m) hbuf[m][tid] = lrelu(acc[m] + b);
    }
    __syncthreads();

    // layer 2: 256 -> 256 (output into aug buffer)
    {
        float acc[16];
#pragma unroll
        for (int m = 0; m < 16; ++m) acc[m] = 0.f;
#pragma unroll 4
        for (int k = 0; k < 256; ++k) {
            float w = fw2[k * 256 + tid];
#pragma unroll
            for (int m = 0; m < 16; ++m) acc[m] += hbuf[m][k] * w;
        }
        float b = fb2[tid];
#pragma unroll
        for (int m = 0; m < 16; ++m) aug[m][tid] = lrelu(acc[m] + b);
    }
    __syncthreads();

    // layer 3: 256 -> 64, residual, write out (skip t = 63)
    {
        int c = tid & 63, sub = tid >> 6;       // 4 subs x 4 rows
        float acc3[4] = {0.f, 0.f, 0.f, 0.f};
#pragma unroll 4
        for (int k = 0; k < 256; ++k) {
            float w = fw3[k * 64 + c];
#pragma unroll
            for (int mm = 0; mm < 4; ++mm) acc3[mm] += aug[sub * 4 + mm][k] * w;
        }
        float b = fb3[c];
#pragma unroll
        for (int mm = 0; mm < 4; ++mm) {
            int m = sub * 4 + mm;
            int n = row0 + m;
            int bb = n >> 11, t = (n >> 5) & 63, a = n & 31;
            if (t < 63) {
                out[(((bb * 32 + a) * 63) + t) * 64 + c] =
                    d_X[n * 64 + c] + acc3[mm] + b;
            }
        }
    }
}

// ---------------------------------------------------------------------------
extern "C" void kernel_launch(void* const* d_in, const int* in_sizes, int n_in,
                              void* d_out, int out_size) {
    (void)in_sizes; (void)n_in; (void)out_size;
    const float* inputs    = (const float*)d_in[0];
    const float* state     = (const float*)d_in[1];
    const float* rel_type  = (const float*)d_in[2];
    // d_in[3] rel_rec, d_in[4] rel_send: structure derived analytically
    const float* msg_fc1_w = (const float*)d_in[5];
    const float* msg_fc1_b = (const float*)d_in[6];
    const float* msg_fc2_w = (const float*)d_in[7];
    const float* msg_fc2_b = (const float*)d_in[8];
    const float* out_fc1_w = (const float*)d_in[9];
    const float* out_fc1_b = (const float*)d_in[10];
    const float* out_fc2_w = (const float*)d_in[11];
    const float* out_fc2_b = (const float*)d_in[12];
    const float* out_fc3_w = (const float*)d_in[13];
    const float* out_fc3_b = (const float*)d_in[14];
    float* out = (float*)d_out;

    k1x<<<(NNODE * 16 + 255) / 256, 256>>>((const float4*)inputs);
    k1g<<<(NEDGE + 255) / 256, 256>>>(state, (const float4*)rel_type);
    k2<<<NNODE / 32, 256>>>(msg_fc1_w, msg_fc1_b);

    cudaFuncSetAttribute(k3, cudaFuncAttributeMaxDynamicSharedMemorySize,
                         K3_SMEM);
    k3<<<NBT * 8, 256, K3_SMEM>>>(msg_fc2_w, msg_fc2_b);

    k5<<<NNODE / 16, 256>>>(out_fc1_w, out_fc1_b, out_fc2_w, out_fc2_b,
                            out_fc3_w, out_fc3_b, out);
}

// round 5
// speedup vs baseline: 1.6930x; 1.6930x over previous
#include <cuda_runtime.h>
#include <cuda_bf16.h>
#include <cstdint>

#define NNODE 8192
#define NEDGE 253952
#define NBT   256

__device__ float d_X  [NNODE * 64];
__device__ float d_PQ [6 * NNODE * 256];
__device__ float d_G  [3 * NEDGE];
__device__ float d_AGG[NNODE * 256];
__device__ __nv_bfloat16 d_Whl[6 * 256 * 256];   // [(e*2+term)][n][k]

__device__ __forceinline__ float lrelu(float v) { return fmaxf(v, 0.01f * v); }

__device__ __forceinline__ uint32_t smem_u32(const void* p) {
    uint32_t a;
    asm("{ .reg .u64 t; cvta.to.shared.u64 t, %1; cvt.u32.u64 %0, t; }" : "=r"(a) : "l"(p));
    return a;
}

#define CP_ASYNC16(dst, src) \
    asm volatile("cp.async.cg.shared.global [%0], [%1], 16;" :: "r"(dst), "l"(src) : "memory")
#define CP_COMMIT() asm volatile("cp.async.commit_group;" ::: "memory")
#define CP_WAIT(n)  asm volatile("cp.async.wait_group %0;" :: "n"(n) : "memory")

#define LDSM_X4(r, a) \
    asm volatile("ldmatrix.sync.aligned.m8n8.x4.shared.b16 {%0,%1,%2,%3}, [%4];" \
        : "=r"((r)[0]), "=r"((r)[1]), "=r"((r)[2]), "=r"((r)[3]) : "r"(a))
#define LDSM_X2(r, a) \
    asm volatile("ldmatrix.sync.aligned.m8n8.x2.shared.b16 {%0,%1}, [%2];" \
        : "=r"((r)[0]), "=r"((r)[1]) : "r"(a))
#define MMA16816(d, a, b) \
    asm volatile("mma.sync.aligned.m16n8k16.row.col.f32.bf16.bf16.f32 " \
        "{%0,%1,%2,%3}, {%4,%5,%6,%7}, {%8,%9}, {%0,%1,%2,%3};" \
        : "+f"((d)[0]), "+f"((d)[1]), "+f"((d)[2]), "+f"((d)[3]) \
        : "r"((a)[0]), "r"((a)[1]), "r"((a)[2]), "r"((a)[3]), "r"((b)[0]), "r"((b)[1]))

// ------------------------- k1x / k1g / k2 / k2w ----------------------------
__global__ void k1x(const float4* __restrict__ in4) {
    int idx = blockIdx.x * blockDim.x + threadIdx.x;
    if (idx >= NNODE * 16) return;
    int n = idx >> 4, q = idx & 15;
    int b = n >> 11, t = (n >> 5) & 63, a = n & 31;
    ((float4*)d_X)[idx] = in4[(((b * 32 + a) * 64) + t) * 16 + q];
}

__global__ void k1g(const float* __restrict__ state, const float4* __restrict__ rt4) {
    int idx = blockIdx.x * blockDim.x + threadIdx.x;
    if (idx >= NEDGE) return;
    int bt = idx / 992, r = idx - bt * 992;
    int b = bt >> 6, t = bt & 63;
    int rec = r / 31, j = r - rec * 31;
    int send = j + (j >= rec);
    const float4 st = *(const float4*)&state[(((b * 32 + send) * 64) + t) * 4];
    const float4* rt = rt4 + (b * 992 + r) * 4;
    float4 r0 = rt[0], r1 = rt[1], r2 = rt[2], r3 = rt[3];
    d_G[0 * NEDGE + idx] = st.x * r0.y + st.y * r1.y + st.z * r2.y + st.w * r3.y;
    d_G[1 * NEDGE + idx] = st.x * r0.z + st.y * r1.z + st.z * r2.z + st.w * r3.z;
    d_G[2 * NEDGE + idx] = st.x * r0.w + st.y * r1.w + st.z * r2.w + st.w * r3.w;
}

__global__ __launch_bounds__(256) void k2(const float* __restrict__ w1,
                                          const float* __restrict__ b1) {
    __shared__ float xs[32][64];
    int row0 = blockIdx.x * 32, tid = threadIdx.x;
    for (int i = tid; i < 32 * 64; i += 256) xs[i >> 6][i & 63] = d_X[row0 * 64 + i];
    __syncthreads();
    for (int chunk = 0; chunk < 6; ++chunk) {
        int e = chunk >> 1, half = chunk & 1;
        const float* W = w1 + ((size_t)((e + 1) * 128 + half * 64)) * 256;
        float acc[32];
#pragma unroll
        for (int m = 0; m < 32; ++m) acc[m] = 0.f;
#pragma unroll 4
        for (int k = 0; k < 64; ++k) {
            float w = W[k * 256 + tid];
#pragma unroll
            for (int m = 0; m < 32; ++m) acc[m] += xs[m][k] * w;
        }
        float bias = (half == 0) ? b1[(e + 1) * 256 + tid] : 0.f;
        float* dst = d_PQ + ((size_t)chunk * NNODE + row0) * 256 + tid;
#pragma unroll
        for (int m = 0; m < 32; ++m) dst[m * 256] = acc[m] + bias;
    }
}

__global__ void k2w(const float* __restrict__ w2) {
    __shared__ float tile[32][33];
    int e = blockIdx.z, kt = blockIdx.x * 32, nt = blockIdx.y * 32;
    int tx = threadIdx.x, ty = threadIdx.y;          // 32 x 8
#pragma unroll
    for (int r = 0; r < 4; ++r)
        tile[ty + r * 8][tx] = w2[((size_t)(e + 1) * 256 + kt + ty + r * 8) * 256 + nt + tx];
    __syncthreads();
#pragma unroll
    for (int r = 0; r < 4; ++r) {
        int n = nt + ty + r * 8;
        float v = tile[tx][ty + r * 8];
        __nv_bfloat16 hi = __float2bfloat16(v);
        __nv_bfloat16 lo = __float2bfloat16(v - __bfloat162float(hi));
        d_Whl[((size_t)(e * 2 + 0) * 256 + n) * 256 + kt + tx] = hi;
        d_Whl[((size_t)(e * 2 + 1) * 256 + n) * 256 + kt + tx] = lo;
    }
}

// ------------------------- k3m: HMMA edge GEMM -----------------------------
// Block = (bt, receiver quad): M=128 (4 rec x 32 slots), N=256, K=256, 3 experts.
// 3-term bf16 hi/lo split (Ah*Bh + Al*Bh + Ah*Bl). 512 threads = 16 warps
// (4 M x 4 N), warp tile 32x64. A rebuilt per K64 chunk in smem (stride 144 B,
// conflict-free ldmatrix); B double-buffered via cp.async from L2-resident d_Whl.
#define OFF_A_LO 18432
#define OFF_B    36864
#define OFF_G    184320
#define OFF_B2   184832
#define K3M_SMEM 185856

__global__ __launch_bounds__(512, 1) void k3m(const float* __restrict__ b2) {
    extern __shared__ char smem[];
    uint32_t sb = smem_u32(smem);
    int tid = threadIdx.x, lane = tid & 31, wid = tid >> 5;
    int mwarp = wid >> 2, nwarp = wid & 3;
    int bt = blockIdx.x >> 3, a0 = (blockIdx.x & 7) << 2;

    float* g_s = (float*)(smem + OFF_G);
    float* b2s = (float*)(smem + OFF_B2);

    float aggv[16];
#pragma unroll
    for (int i = 0; i < 16; ++i) aggv[i] = 0.f;

    // prefetch one K64 chunk of B (hi+lo terms) into ring buffer cc&1
    auto loadB = [&](int cc) {
        int e = cc >> 2, kc = cc & 3;
        uint32_t dbase = sb + OFF_B + (uint32_t)(cc & 1) * 73728u;
#pragma unroll
        for (int it = 0; it < 8; ++it) {
            int i = tid + it * 512;
            int term = i >> 11, r = i & 2047, n = r >> 3, g8 = r & 7;
            const __nv_bfloat16* src = d_Whl + ((size_t)(e * 2 + term)) * 65536
                                     + n * 256 + kc * 64 + g8 * 8;
            uint32_t dst = dbase + (uint32_t)term * 36864u + (uint32_t)n * 144u
                         + (uint32_t)g8 * 16u;
            CP_ASYNC16(dst, src);
        }
        CP_COMMIT();
    };

    // build A chunk: 128 rows x 64 k, hi + lo bf16
    auto buildA = [&](int e, int kc) {
        int m = tid >> 2, rec = a0 + (m >> 5), j = m & 31;
        bool valid = j < 31;
        int send = valid ? (j + (j >= rec)) : 0;
        const float4* Pb = (const float4*)(d_PQ + ((size_t)(e * 2) * NNODE + bt * 32 + send) * 256
                                           + kc * 64) + (tid & 3) * 4;
        const float4* Qb = (const float4*)(d_PQ + ((size_t)(e * 2 + 1) * NNODE + bt * 32 + rec) * 256
                                           + kc * 64) + (tid & 3) * 4;
        char* arow = smem + m * 144 + (tid & 3) * 32;
#pragma unroll
        for (int q = 0; q < 4; ++q) {
            float4 p = Pb[q], qq = Qb[q];
            float v0 = lrelu(p.x + qq.x), v1 = lrelu(p.y + qq.y);
            float v2 = lrelu(p.z + qq.z), v3 = lrelu(p.w + qq.w);
            if (!valid) { v0 = v1 = v2 = v3 = 0.f; }
            __nv_bfloat162 h0 = __floats2bfloat162_rn(v0, v1);
            __nv_bfloat162 h1 = __floats2bfloat162_rn(v2, v3);
            __nv_bfloat162 l0 = __floats2bfloat162_rn(v0 - __bfloat162float(h0.x),
                                                      v1 - __bfloat162float(h0.y));
            __nv_bfloat162 l1 = __floats2bfloat162_rn(v2 - __bfloat162float(h1.x),
                                                      v3 - __bfloat162float(h1.y));
            *(uint32_t*)(arow + q * 8 + 0) = *(uint32_t*)&h0;
            *(uint32_t*)(arow + q * 8 + 4) = *(uint32_t*)&h1;
            *(uint32_t*)(arow + OFF_A_LO + q * 8 + 0) = *(uint32_t*)&l0;
            *(uint32_t*)(arow + OFF_A_LO + q * 8 + 4) = *(uint32_t*)&l1;
        }
    };

    loadB(0);

    for (int e = 0; e < 3; ++e) {
        float acc[2][8][4];
#pragma unroll
        for (int ms = 0; ms < 2; ++ms)
#pragma unroll
            for (int ns = 0; ns < 8; ++ns)
#pragma unroll
                for (int c = 0; c < 4; ++c) acc[ms][ns][c] = 0.f;

        for (int kc = 0; kc < 4; ++kc) {
            int cc = e * 4 + kc;
            if (cc + 1 < 12) loadB(cc + 1);
            buildA(e, kc);
            if (kc == 0) {
                if (tid < 128) {
                    int grp = tid >> 5, jj = tid & 31;
                    g_s[tid] = (jj < 31)
                        ? d_G[(size_t)e * NEDGE + bt * 992 + (a0 + grp) * 31 + jj] : 0.f;
                } else if (tid < 384) {
                    int c = tid - 128;
                    b2s[c] = b2[(e + 1) * 256 + c];
                }
            }
            if (cc + 1 < 12) { CP_WAIT(1); } else { CP_WAIT(0); }
            __syncthreads();

            uint32_t a_l = sb + (uint32_t)(mwarp * 32 + (lane & 7) + ((lane >> 3) & 1) * 8) * 144u
                         + ((lane >> 4) & 1) * 16u;
            uint32_t b_l = sb + OFF_B + (uint32_t)(cc & 1) * 73728u
                         + (uint32_t)(nwarp * 64 + (lane & 7)) * 144u
                         + ((lane >> 3) & 1) * 16u;
#pragma unroll
            for (int ks = 0; ks < 4; ++ks) {
                uint32_t ah0[4], ah1[4], al0[4], al1[4];
                LDSM_X4(ah0, a_l + ks * 32);
                LDSM_X4(ah1, a_l + 16 * 144 + ks * 32);
                LDSM_X4(al0, a_l + OFF_A_LO + ks * 32);
                LDSM_X4(al1, a_l + OFF_A_LO + 16 * 144 + ks * 32);
#pragma unroll
                for (int nst = 0; nst < 8; ++nst) {
                    uint32_t bh[2], bl[2];
                    LDSM_X2(bh, b_l + nst * 1152u + ks * 32);
                    LDSM_X2(bl, b_l + 36864u + nst * 1152u + ks * 32);
                    MMA16816(acc[0][nst], ah0, bh);
                    MMA16816(acc[1][nst], ah1, bh);
                    MMA16816(acc[0][nst], al0, bh);
                    MMA16816(acc[1][nst], al1, bh);
                    MMA16816(acc[0][nst], ah0, bl);
                    MMA16816(acc[1][nst], ah1, bl);
                }
            }
            __syncthreads();
        }

        // epilogue: bias + lrelu + gate, reduce 32 rows (one receiver) per warp
        float g00 = g_s[mwarp * 32 + (lane >> 2)];
        float g01 = g_s[mwarp * 32 + (lane >> 2) + 8];
        float g10 = g_s[mwarp * 32 + 16 + (lane >> 2)];
        float g11 = g_s[mwarp * 32 + 24 + (lane >> 2)];
#pragma unroll
        for (int nst = 0; nst < 8; ++nst) {
            int c0 = nwarp * 64 + nst * 8 + (lane & 3) * 2;
            float b0v = b2s[c0], b1v = b2s[c0 + 1];
            float s0 = lrelu(acc[0][nst][0] + b0v) * g00 + lrelu(acc[0][nst][2] + b0v) * g01
                     + lrelu(acc[1][nst][0] + b0v) * g10 + lrelu(acc[1][nst][2] + b0v) * g11;
            float s1 = lrelu(acc[0][nst][1] + b1v) * g00 + lrelu(acc[0][nst][3] + b1v) * g01
                     + lrelu(acc[1][nst][1] + b1v) * g10 + lrelu(acc[1][nst][3] + b1v) * g11;
            s0 += __shfl_xor_sync(~0u, s0, 4);  s1 += __shfl_xor_sync(~0u, s1, 4);
            s0 += __shfl_xor_sync(~0u, s0, 8);  s1 += __shfl_xor_sync(~0u, s1, 8);
            s0 += __shfl_xor_sync(~0u, s0, 16); s1 += __shfl_xor_sync(~0u, s1, 16);
            aggv[nst * 2] += s0; aggv[nst * 2 + 1] += s1;
        }
        __syncthreads();   // protect g_s/b2s before next expert reloads them
    }

    if (lane < 4) {
        int node = bt * 32 + a0 + mwarp;
#pragma unroll
        for (int nst = 0; nst < 8; ++nst) {
            int c = nwarp * 64 + nst * 8 + lane * 2;
            d_AGG[(size_t)node * 256 + c]     = aggv[nst * 2];
            d_AGG[(size_t)node * 256 + c + 1] = aggv[nst * 2 + 1];
        }
    }
}

// ------------------------- k5: output MLP + residual -----------------------
__global__ __launch_bounds__(256) void k5(const float* __restrict__ fw1,
                                          const float* __restrict__ fb1,
                                          const float* __restrict__ fw2,
                                          const float* __restrict__ fb2,
                                          const float* __restrict__ fw3,
                                          const float* __restrict__ fb3,
                                          float* __restrict__ out) {
    __shared__ float aug[16][320];
    __shared__ float hbuf[16][256];
    int row0 = blockIdx.x * 16, tid = threadIdx.x;
    for (int i = tid; i < 16 * 64; i += 256) aug[i >> 6][i & 63] = d_X[row0 * 64 + i];
    for (int i = tid; i < 16 * 256; i += 256)
        aug[i >> 8][64 + (i & 255)] = d_AGG[(size_t)row0 * 256 + i];
    __syncthreads();
    {
        float acc[16];
#pragma unroll
        for (int m = 0; m < 16; ++m) acc[m] = 0.f;
#pragma unroll 4
        for (int k = 0; k < 320; ++k) {
            float w = fw1[k * 256 + tid];
#pragma unroll
            for (int m = 0; m < 16; ++m) acc[m] += aug[m][k] * w;
        }
        float b = fb1[tid];
#pragma unroll
        for (int m = 0; m < 16; ++m) hbuf[m][tid] = lrelu(acc[m] + b);
    }
    __syncthreads();
    {
        float acc[16];
#pragma unroll
        for (int m = 0; m < 16; ++m) acc[m] = 0.f;
#pragma unroll 4
        for (int k = 0; k < 256; ++k) {
            float w = fw2[k * 256 + tid];
#pragma unroll
            for (int m = 0; m < 16; ++m) acc[m] += hbuf[m][k] * w;
        }
        float b = fb2[tid];
#pragma unroll
        for (int m = 0; m < 16; ++m) aug[m][tid] = lrelu(acc[m] + b);
    }
    __syncthreads();
    {
        int c = tid & 63, sub = tid >> 6;
        float acc3[4] = {0.f, 0.f, 0.f, 0.f};
#pragma unroll 4
        for (int k = 0; k < 256; ++k) {
            float w = fw3[k * 64 + c];
#pragma unroll
            for (int mm = 0; mm < 4; ++mm) acc3[mm] += aug[sub * 4 + mm][k] * w;
        }
        float b = fb3[c];
#pragma unroll
        for (int mm = 0; mm < 4; ++mm) {
            int n = row0 + sub * 4 + mm;
            int bb = n >> 11, t = (n >> 5) & 63, a = n & 31;
            if (t < 63)
                out[(((bb * 32 + a) * 63) + t) * 64 + c] = d_X[n * 64 + c] + acc3[mm] + b;
        }
    }
}

// ---------------------------------------------------------------------------
extern "C" void kernel_launch(void* const* d_in, const int* in_sizes, int n_in,
                              void* d_out, int out_size) {
    (void)in_sizes; (void)n_in; (void)out_size;
    const float* inputs    = (const float*)d_in[0];
    const float* state     = (const float*)d_in[1];
    const float* rel_type  = (const float*)d_in[2];
    const float* msg_fc1_w = (const float*)d_in[5];
    const float* msg_fc1_b = (const float*)d_in[6];
    const float* msg_fc2_w = (const float*)d_in[7];
    const float* msg_fc2_b = (const float*)d_in[8];
    const float* out_fc1_w = (const float*)d_in[9];
    const float* out_fc1_b = (const float*)d_in[10];
    const float* out_fc2_w = (const float*)d_in[11];
    const float* out_fc2_b = (const float*)d_in[12];
    const float* out_fc3_w = (const float*)d_in[13];
    const float* out_fc3_b = (const float*)d_in[14];
    float* out = (float*)d_out;

    k1x<<<(NNODE * 16 + 255) / 256, 256>>>((const float4*)inputs);
    k1g<<<(NEDGE + 255) / 256, 256>>>(state, (const float4*)rel_type);
    k2<<<NNODE / 32, 256>>>(msg_fc1_w, msg_fc1_b);
    k2w<<<dim3(8, 8, 3), dim3(32, 8)>>>(msg_fc2_w);

    cudaFuncSetAttribute(k3m, cudaFuncAttributeMaxDynamicSharedMemorySize, K3M_SMEM);
    k3m<<<NBT * 8, 512, K3M_SMEM>>>(msg_fc2_b);

    k5<<<NNODE / 16, 256>>>(out_fc1_w, out_fc1_b, out_fc2_w, out_fc2_b,
                            out_fc3_w, out_fc3_b, out);
}

// round 7
// speedup vs baseline: 2.8927x; 1.7086x over previous
#include <cuda_runtime.h>
#include <cuda_fp16.h>
#include <cstdint>

#define NNODE 8192
#define NEDGE 253952
#define NBT   256

__device__ float d_X  [NNODE * 64];
__device__ float d_PQ [6 * NNODE * 256];
__device__ float d_G  [3 * NEDGE];
__device__ float d_AGG[NNODE * 256];
__device__ __half d_Wh[3 * 256 * 256];   // [e][n][k] fp16

__device__ __forceinline__ float lrelu(float v) { return fmaxf(v, 0.01f * v); }

__device__ __forceinline__ uint32_t smem_u32(const void* p) {
    uint32_t a;
    asm("{ .reg .u64 t; cvta.to.shared.u64 t, %1; cvt.u32.u64 %0, t; }" : "=r"(a) : "l"(p));
    return a;
}

#define CP_ASYNC16(dst, src) \
    asm volatile("cp.async.cg.shared.global [%0], [%1], 16;" :: "r"(dst), "l"(src) : "memory")
#define CP_COMMIT() asm volatile("cp.async.commit_group;" ::: "memory")
#define CP_WAIT(n)  asm volatile("cp.async.wait_group %0;" :: "n"(n) : "memory")

#define LDSM_X4(r, a) \
    asm volatile("ldmatrix.sync.aligned.m8n8.x4.shared.b16 {%0,%1,%2,%3}, [%4];" \
        : "=r"((r)[0]), "=r"((r)[1]), "=r"((r)[2]), "=r"((r)[3]) : "r"(a))
#define MMA16816(d, a, b) \
    asm volatile("mma.sync.aligned.m16n8k16.row.col.f32.f16.f16.f32 " \
        "{%0,%1,%2,%3}, {%4,%5,%6,%7}, {%8,%9}, {%0,%1,%2,%3};" \
        : "+f"((d)[0]), "+f"((d)[1]), "+f"((d)[2]), "+f"((d)[3]) \
        : "r"((a)[0]), "r"((a)[1]), "r"((a)[2]), "r"((a)[3]), "r"((b)[0]), "r"((b)[1]))

// ------------------------- k1x / k1g / k2 ----------------------------------
__global__ void k1x(const float4* __restrict__ in4) {
    int idx = blockIdx.x * blockDim.x + threadIdx.x;
    if (idx >= NNODE * 16) return;
    int n = idx >> 4, q = idx & 15;
    int b = n >> 11, t = (n >> 5) & 63, a = n & 31;
    ((float4*)d_X)[idx] = in4[(((b * 32 + a) * 64) + t) * 16 + q];
}

__global__ void k1g(const float* __restrict__ state, const float4* __restrict__ rt4) {
    int idx = blockIdx.x * blockDim.x + threadIdx.x;
    if (idx >= NEDGE) return;
    int bt = idx / 992, r = idx - bt * 992;
    int b = bt >> 6, t = bt & 63;
    int rec = r / 31, j = r - rec * 31;
    int send = j + (j >= rec);
    const float4 st = *(const float4*)&state[(((b * 32 + send) * 64) + t) * 4];
    const float4* rt = rt4 + (b * 992 + r) * 4;
    float4 r0 = rt[0], r1 = rt[1], r2 = rt[2], r3 = rt[3];
    d_G[0 * NEDGE + idx] = st.x * r0.y + st.y * r1.y + st.z * r2.y + st.w * r3.y;
    d_G[1 * NEDGE + idx] = st.x * r0.z + st.y * r1.z + st.z * r2.z + st.w * r3.z;
    d_G[2 * NEDGE + idx] = st.x * r0.w + st.y * r1.w + st.z * r2.w + st.w * r3.w;
}

__global__ __launch_bounds__(256) void k2(const float* __restrict__ w1,
                                          const float* __restrict__ b1) {
    __shared__ float xs[32][64];
    int row0 = blockIdx.x * 32, tid = threadIdx.x;
    for (int i = tid; i < 32 * 64; i += 256) xs[i >> 6][i & 63] = d_X[row0 * 64 + i];
    __syncthreads();
    for (int chunk = 0; chunk < 6; ++chunk) {
        int e = chunk >> 1, half = chunk & 1;
        const float* W = w1 + ((size_t)((e + 1) * 128 + half * 64)) * 256;
        float acc[32];
#pragma unroll
        for (int m = 0; m < 32; ++m) acc[m] = 0.f;
#pragma unroll 4
        for (int k = 0; k < 64; ++k) {
            float w = W[k * 256 + tid];
#pragma unroll
            for (int m = 0; m < 32; ++m) acc[m] += xs[m][k] * w;
        }
        float bias = (half == 0) ? b1[(e + 1) * 256 + tid] : 0.f;
        float* dst = d_PQ + ((size_t)chunk * NNODE + row0) * 256 + tid;
#pragma unroll
        for (int m = 0; m < 32; ++m) dst[m * 256] = acc[m] + bias;
    }
}

// --------------- k2w: W2 transpose -> fp16 [e][n][k] -----------------------
__global__ void k2w(const float* __restrict__ w2) {
    __shared__ float tile[32][33];
    int e = blockIdx.z, kt = blockIdx.x * 32, nt = blockIdx.y * 32;
    int tx = threadIdx.x, ty = threadIdx.y;          // 32 x 8
#pragma unroll
    for (int r = 0; r < 4; ++r)
        tile[ty + r * 8][tx] = w2[((size_t)(e + 1) * 256 + kt + ty + r * 8) * 256 + nt + tx];
    __syncthreads();
#pragma unroll
    for (int r = 0; r < 4; ++r) {
        int n = nt + ty + r * 8;
        d_Wh[((size_t)e * 256 + n) * 256 + kt + tx] = __float2half(tile[tx][ty + r * 8]);
    }
}

// ------------------------- k3f: fp16 HMMA edge GEMM ------------------------
// Block = (bt, receiver quad): M=128, N=256, K=256, 3 experts, fp16 1-term.
// 16 warps (4M x 4N), warp tile 32x64. A TRIPLE-buffered (race-free with one
// sync/chunk), B 3-slot cp.async ring (prefetch distance 2), P/Q SMEM-staged.
#define OFF_A    0            // 3 x 18432
#define OFF_B    55296        // 3 x 36864
#define OFF_PQ   165888       // 36 rows x 1040 B (P rows 0-31, Q rows 32-35)
#define OFF_G    203328       // 2 x 512
#define OFF_B2   204352       // 2 x 1024
#define K3F_SMEM 206400

__global__ __launch_bounds__(512, 1) void k3f(const float* __restrict__ b2) {
    extern __shared__ char smem[];
    uint32_t sb = smem_u32(smem);
    int tid = threadIdx.x, lane = tid & 31, wid = tid >> 5;
    int mwarp = wid >> 2, nwarp = wid & 3;
    int bt = blockIdx.x >> 3, a0 = (blockIdx.x & 7) << 2;

    // stage P (32 rows) + Q (4 receiver rows) fp32 into smem via cp.async
    auto stagePQ = [&](int e) {
        const float* Psrc = d_PQ + ((size_t)(e * 2) * NNODE + bt * 32) * 256;
        const float* Qsrc = d_PQ + ((size_t)(e * 2 + 1) * NNODE + bt * 32 + a0) * 256;
        for (int i = tid; i < 2048; i += 512) {
            int r = i >> 6, q = i & 63;
            CP_ASYNC16(sb + OFF_PQ + r * 1040 + q * 16, (const char*)(Psrc + r * 256 + q * 4));
        }
        if (tid < 256) {
            int r = tid >> 6, q = tid & 63;
            CP_ASYNC16(sb + OFF_PQ + (32 + r) * 1040 + q * 16, (const char*)(Qsrc + r * 256 + q * 4));
        }
        CP_COMMIT();
    };
    auto stageGB = [&](int e) {
        int sl = e & 1;
        if (tid < 128) {
            int grp = tid >> 5, j = tid & 31;
            ((float*)(smem + OFF_G))[sl * 128 + tid] = (j < 31)
                ? d_G[(size_t)e * NEDGE + bt * 992 + (a0 + grp) * 31 + j] : 0.f;
        } else if (tid < 384) {
            int c = tid - 128;
            ((float*)(smem + OFF_B2))[sl * 256 + c] = b2[(e + 1) * 256 + c];
        }
    };
    auto loadB = [&](int cc) {
        int e = cc >> 2, kc = cc & 3;
        uint32_t db = sb + OFF_B + (uint32_t)(cc % 3) * 36864u;
        const __half* S = d_Wh + (size_t)e * 65536 + kc * 64;
        for (int i = tid; i < 2048; i += 512) {          // 256 rows x 8 x 16B
            int n = i >> 3, g8 = i & 7;
            CP_ASYNC16(db + n * 144 + g8 * 16, (const char*)(S + n * 256 + g8 * 8));
        }
        CP_COMMIT();
    };
    // build A chunk (128 x 64 fp16) from SMEM-staged P/Q into buffer cc%3
    auto buildA = [&](int cc) {
        int kc = cc & 3;
        int m = tid >> 2, sub = tid & 3;
        int rec = a0 + (m >> 5), j = m & 31;
        bool valid = j < 31;
        int send = valid ? (j + (j >= rec)) : 0;
        const float4* P = (const float4*)(smem + OFF_PQ + send * 1040) + kc * 16 + sub * 4;
        const float4* Q = (const float4*)(smem + OFF_PQ + (32 + (m >> 5)) * 1040) + kc * 16 + sub * 4;
        char* dst = smem + OFF_A + (cc % 3) * 18432 + m * 144 + sub * 32;
#pragma unroll
        for (int q = 0; q < 4; ++q) {
            float4 p = P[q], qq = Q[q];
            float v0 = lrelu(p.x + qq.x), v1 = lrelu(p.y + qq.y);
            float v2 = lrelu(p.z + qq.z), v3 = lrelu(p.w + qq.w);
            if (!valid) { v0 = v1 = v2 = v3 = 0.f; }
            __half2 h0 = __floats2half2_rn(v0, v1);
            __half2 h1 = __floats2half2_rn(v2, v3);
            *(uint32_t*)(dst + q * 8)     = *(uint32_t*)&h0;
            *(uint32_t*)(dst + q * 8 + 4) = *(uint32_t*)&h1;
        }
    };

    float aggv[16];
#pragma unroll
    for (int i = 0; i < 16; ++i) aggv[i] = 0.f;

    // prologue
    stagePQ(0); stageGB(0);
    CP_WAIT(0);
    __syncthreads();
    loadB(0); loadB(1);
    buildA(0);

    float acc[2][8][4];

    for (int cc = 0; cc < 12; ++cc) {
        int e = cc >> 2, kc = cc & 3;
        if (kc == 0) {
#pragma unroll
            for (int ms = 0; ms < 2; ++ms)
#pragma unroll
                for (int ns = 0; ns < 8; ++ns)
#pragma unroll
                    for (int c = 0; c < 4; ++c) acc[ms][ns][c] = 0.f;
        }
        // expert boundary: restage P/Q and gates for e+1 before building its A
        if (kc == 3 && e < 2) {
            stagePQ(e + 1); stageGB(e + 1);
            CP_WAIT(0);
            __syncthreads();
        }
        if (cc < 11) buildA(cc + 1);
        if (cc >= 10) { CP_WAIT(0); } else { CP_WAIT(1); }
        __syncthreads();
        if (cc < 10) loadB(cc + 2);

        uint32_t a_l = sb + OFF_A + (uint32_t)(cc % 3) * 18432u
                     + (uint32_t)(mwarp * 32 + (lane & 7) + ((lane >> 3) & 1) * 8) * 144u
                     + ((lane >> 4) & 1) * 16u;
        uint32_t b_l = sb + OFF_B + (uint32_t)(cc % 3) * 36864u
                     + (uint32_t)(nwarp * 64 + (lane & 7) + ((lane >> 4) & 1) * 8) * 144u
                     + ((lane >> 3) & 1) * 16u;
#pragma unroll
        for (int ks = 0; ks < 4; ++ks) {
            uint32_t a0f[4], a1f[4];
            LDSM_X4(a0f, a_l + ks * 32);
            LDSM_X4(a1f, a_l + 16 * 144 + ks * 32);
#pragma unroll
            for (int p = 0; p < 4; ++p) {
                uint32_t bf[4];
                LDSM_X4(bf, b_l + p * 2304 + ks * 32);
                MMA16816(acc[0][2 * p],     a0f, bf);
                MMA16816(acc[0][2 * p + 1], a0f, bf + 2);
                MMA16816(acc[1][2 * p],     a1f, bf);
                MMA16816(acc[1][2 * p + 1], a1f, bf + 2);
            }
        }

        if (kc == 3) {
            // epilogue: bias + lrelu + gate, reduce 32 rows (one receiver)/warp
            const float* g_s = (const float*)(smem + OFF_G) + (e & 1) * 128;
            const float* b2s = (const float*)(smem + OFF_B2) + (e & 1) * 256;
            float g00 = g_s[mwarp * 32 + (lane >> 2)];
            float g01 = g_s[mwarp * 32 + (lane >> 2) + 8];
            float g10 = g_s[mwarp * 32 + 16 + (lane >> 2)];
            float g11 = g_s[mwarp * 32 + 24 + (lane >> 2)];
#pragma unroll
            for (int nst = 0; nst < 8; ++nst) {
                int c0 = nwarp * 64 + nst * 8 + (lane & 3) * 2;
                float b0v = b2s[c0], b1v = b2s[c0 + 1];
                float s0 = lrelu(acc[0][nst][0] + b0v) * g00 + lrelu(acc[0][nst][2] + b0v) * g01
                         + lrelu(acc[1][nst][0] + b0v) * g10 + lrelu(acc[1][nst][2] + b0v) * g11;
                float s1 = lrelu(acc[0][nst][1] + b1v) * g00 + lrelu(acc[0][nst][3] + b1v) * g01
                         + lrelu(acc[1][nst][1] + b1v) * g10 + lrelu(acc[1][nst][3] + b1v) * g11;
                s0 += __shfl_xor_sync(~0u, s0, 4);  s1 += __shfl_xor_sync(~0u, s1, 4);
                s0 += __shfl_xor_sync(~0u, s0, 8);  s1 += __shfl_xor_sync(~0u, s1, 8);
                s0 += __shfl_xor_sync(~0u, s0, 16); s1 += __shfl_xor_sync(~0u, s1, 16);
                aggv[nst * 2] += s0; aggv[nst * 2 + 1] += s1;
            }
        }
    }

    if (lane < 4) {
        int node = bt * 32 + a0 + mwarp;
#pragma unroll
        for (int nst = 0; nst < 8; ++nst) {
            int c = nwarp * 64 + nst * 8 + lane * 2;
            d_AGG[(size_t)node * 256 + c]     = aggv[nst * 2];
            d_AGG[(size_t)node * 256 + c + 1] = aggv[nst * 2 + 1];
        }
    }
}

// ------------------------- k5: output MLP + residual -----------------------
__global__ __launch_bounds__(256) void k5(const float* __restrict__ fw1,
                                          const float* __restrict__ fb1,
                                          const float* __restrict__ fw2,
                                          const float* __restrict__ fb2,
                                          const float* __restrict__ fw3,
                                          const float* __restrict__ fb3,
                                          float* __restrict__ out) {
    __shared__ float aug[16][320];
    __shared__ float hbuf[16][256];
    int row0 = blockIdx.x * 16, tid = threadIdx.x;
    for (int i = tid; i < 16 * 64; i += 256) aug[i >> 6][i & 63] = d_X[row0 * 64 + i];
    for (int i = tid; i < 16 * 256; i += 256)
        aug[i >> 8][64 + (i & 255)] = d_AGG[(size_t)row0 * 256 + i];
    __syncthreads();
    {
        float acc[16];
#pragma unroll
        for (int m = 0; m < 16; ++m) acc[m] = 0.f;
#pragma unroll 4
        for (int k = 0; k < 320; ++k) {
            float w = fw1[k * 256 + tid];
#pragma unroll
            for (int m = 0; m < 16; ++m) acc[m] += aug[m][k] * w;
        }
        float b = fb1[tid];
#pragma unroll
        for (int m = 0; m < 16; ++m) hbuf[m][tid] = lrelu(acc[m] + b);
    }
    __syncthreads();
    {
        float acc[16];
#pragma unroll
        for (int m = 0; m < 16; ++m) acc[m] = 0.f;
#pragma unroll 4
        for (int k = 0; k < 256; ++k) {
            float w = fw2[k * 256 + tid];
#pragma unroll
            for (int m = 0; m < 16; ++m) acc[m] += hbuf[m][k] * w;
        }
        float b = fb2[tid];
#pragma unroll
        for (int m = 0; m < 16; ++m) aug[m][tid] = lrelu(acc[m] + b);
    }
    __syncthreads();
    {
        int c = tid & 63, sub = tid >> 6;
        float acc3[4] = {0.f, 0.f, 0.f, 0.f};
#pragma unroll 4
        for (int k = 0; k < 256; ++k) {
            float w = fw3[k * 64 + c];
#pragma unroll
            for (int mm = 0; mm < 4; ++mm) acc3[mm] += aug[sub * 4 + mm][k] * w;
        }
        float b = fb3[c];
#pragma unroll
        for (int mm = 0; mm < 4; ++mm) {
            int n = row0 + sub * 4 + mm;
            int bb = n >> 11, t = (n >> 5) & 63, a = n & 31;
            if (t < 63)
                out[(((bb * 32 + a) * 63) + t) * 64 + c] = d_X[n * 64 + c] + acc3[mm] + b;
        }
    }
}

// ---------------------------------------------------------------------------
extern "C" void kernel_launch(void* const* d_in, const int* in_sizes, int n_in,
                              void* d_out, int out_size) {
    (void)in_sizes; (void)n_in; (void)out_size;
    const float* inputs    = (const float*)d_in[0];
    const float* state     = (const float*)d_in[1];
    const float* rel_type  = (const float*)d_in[2];
    const float* msg_fc1_w = (const float*)d_in[5];
    const float* msg_fc1_b = (const float*)d_in[6];
    const float* msg_fc2_w = (const float*)d_in[7];
    const float* msg_fc2_b = (const float*)d_in[8];
    const float* out_fc1_w = (const float*)d_in[9];
    const float* out_fc1_b = (const float*)d_in[10];
    const float* out_fc2_w = (const float*)d_in[11];
    const float* out_fc2_b = (const float*)d_in[12];
    const float* out_fc3_w = (const float*)d_in[13];
    const float* out_fc3_b = (const float*)d_in[14];
    float* out = (float*)d_out;

    k1x<<<(NNODE * 16 + 255) / 256, 256>>>((const float4*)inputs);
    k1g<<<(NEDGE + 255) / 256, 256>>>(state, (const float4*)rel_type);
    k2<<<NNODE / 32, 256>>>(msg_fc1_w, msg_fc1_b);
    k2w<<<dim3(8, 8, 3), dim3(32, 8)>>>(msg_fc2_w);

    cudaFuncSetAttribute(k3f, cudaFuncAttributeMaxDynamicSharedMemorySize, K3F_SMEM);
    k3f<<<NBT * 8, 512, K3F_SMEM>>>(msg_fc2_b);

    k5<<<NNODE / 16, 256>>>(out_fc1_w, out_fc1_b, out_fc2_w, out_fc2_b,
                            out_fc3_w, out_fc3_b, out);
}

// round 8
// speedup vs baseline: 3.3528x; 1.1590x over previous
#include <cuda_runtime.h>
#include <cuda_fp16.h>
#include <cstdint>

#define NNODE 8192
#define NEDGE 253952
#define NBT   256

__device__ float  d_X  [NNODE * 64];
__device__ __half d_PQh[6 * NNODE * 256];      // [e*2+half][node][256] fp16
__device__ float  d_G  [3 * NEDGE];
__device__ float  d_AGGe[3 * NNODE * 256];     // per-expert partial agg
__device__ __half d_Wh[3 * 256 * 256];         // [e][n][k] fp16

__device__ __forceinline__ float lrelu(float v) { return fmaxf(v, 0.01f * v); }

__device__ __forceinline__ uint32_t smem_u32(const void* p) {
    uint32_t a;
    asm("{ .reg .u64 t; cvta.to.shared.u64 t, %1; cvt.u32.u64 %0, t; }" : "=r"(a) : "l"(p));
    return a;
}

#define CP_ASYNC16(dst, src) \
    asm volatile("cp.async.cg.shared.global [%0], [%1], 16;" :: "r"(dst), "l"(src) : "memory")
#define CP_COMMIT() asm volatile("cp.async.commit_group;" ::: "memory")
#define CP_WAIT(n)  asm volatile("cp.async.wait_group %0;" :: "n"(n) : "memory")

#define LDSM_X4(r, a) \
    asm volatile("ldmatrix.sync.aligned.m8n8.x4.shared.b16 {%0,%1,%2,%3}, [%4];" \
        : "=r"((r)[0]), "=r"((r)[1]), "=r"((r)[2]), "=r"((r)[3]) : "r"(a))
#define MMA16816(d, a, b) \
    asm volatile("mma.sync.aligned.m16n8k16.row.col.f32.f16.f16.f32 " \
        "{%0,%1,%2,%3}, {%4,%5,%6,%7}, {%8,%9}, {%0,%1,%2,%3};" \
        : "+f"((d)[0]), "+f"((d)[1]), "+f"((d)[2]), "+f"((d)[3]) \
        : "r"((a)[0]), "r"((a)[1]), "r"((a)[2]), "r"((a)[3]), "r"((b)[0]), "r"((b)[1]))

// ------------------------- k1x / k1g -------------------------------------
__global__ void k1x(const float4* __restrict__ in4) {
    int idx = blockIdx.x * blockDim.x + threadIdx.x;
    if (idx >= NNODE * 16) return;
    int n = idx >> 4, q = idx & 15;
    int b = n >> 11, t = (n >> 5) & 63, a = n & 31;
    ((float4*)d_X)[idx] = in4[(((b * 32 + a) * 64) + t) * 16 + q];
}

__global__ void k1g(const float* __restrict__ state, const float4* __restrict__ rt4) {
    int idx = blockIdx.x * blockDim.x + threadIdx.x;
    if (idx >= NEDGE) return;
    int bt = idx / 992, r = idx - bt * 992;
    int b = bt >> 6, t = bt & 63;
    int rec = r / 31, j = r - rec * 31;
    int send = j + (j >= rec);
    const float4 st = *(const float4*)&state[(((b * 32 + send) * 64) + t) * 4];
    const float4* rt = rt4 + (b * 992 + r) * 4;
    float4 r0 = rt[0], r1 = rt[1], r2 = rt[2], r3 = rt[3];
    d_G[0 * NEDGE + idx] = st.x * r0.y + st.y * r1.y + st.z * r2.y + st.w * r3.y;
    d_G[1 * NEDGE + idx] = st.x * r0.z + st.y * r1.z + st.z * r2.z + st.w * r3.z;
    d_G[2 * NEDGE + idx] = st.x * r0.w + st.y * r1.w + st.z * r2.w + st.w * r3.w;
}

// ------------------------- k2: P/Q node GEMMs -> fp16 ----------------------
__global__ __launch_bounds__(256) void k2(const float* __restrict__ w1,
                                          const float* __restrict__ b1) {
    __shared__ float xs[32][64];
    int row0 = blockIdx.x * 32, tid = threadIdx.x;
    for (int i = tid; i < 32 * 64; i += 256) xs[i >> 6][i & 63] = d_X[row0 * 64 + i];
    __syncthreads();
    for (int chunk = 0; chunk < 6; ++chunk) {
        int e = chunk >> 1, half = chunk & 1;
        const float* W = w1 + ((size_t)((e + 1) * 128 + half * 64)) * 256;
        float acc[32];
#pragma unroll
        for (int m = 0; m < 32; ++m) acc[m] = 0.f;
#pragma unroll 4
        for (int k = 0; k < 64; ++k) {
            float w = W[k * 256 + tid];
#pragma unroll
            for (int m = 0; m < 32; ++m) acc[m] += xs[m][k] * w;
        }
        float bias = (half == 0) ? b1[(e + 1) * 256 + tid] : 0.f;
        __half* dst = d_PQh + ((size_t)chunk * NNODE + row0) * 256 + tid;
#pragma unroll
        for (int m = 0; m < 32; ++m) dst[m * 256] = __float2half(acc[m] + bias);
    }
}

// --------------- k2w: W2 transpose -> fp16 [e][n][k] -----------------------
__global__ void k2w(const float* __restrict__ w2) {
    __shared__ float tile[32][33];
    int e = blockIdx.z, kt = blockIdx.x * 32, nt = blockIdx.y * 32;
    int tx = threadIdx.x, ty = threadIdx.y;          // 32 x 8
#pragma unroll
    for (int r = 0; r < 4; ++r)
        tile[ty + r * 8][tx] = w2[((size_t)(e + 1) * 256 + kt + ty + r * 8) * 256 + nt + tx];
    __syncthreads();
#pragma unroll
    for (int r = 0; r < 4; ++r) {
        int n = nt + ty + r * 8;
        d_Wh[((size_t)e * 256 + n) * 256 + kt + tx] = __float2half(tile[tx][ty + r * 8]);
    }
}

// ------------------------- k3g: B-resident fp16 HMMA edge GEMM -------------
// Grid = 3 experts x 48 bt-groups (144 blocks, 1 wave). Each block: load its
// expert's full B (256n x 256k fp16, 528B rows) into SMEM ONCE, then stream
// (bt,quad) A-tiles (M=128, built from fp16 P/Q staged per-bt/per-tile).
// A double-buffered per K64 chunk; pattern per kc: {build(kc+1)||stage; mma(kc); sync}.
#define SB_B    0            // 256 x 528 = 135168
#define SB_A    135168       // 2 x 128 x 144 = 36864
#define SB_P    172032       // 2 x 32 x 528 = 33792
#define SB_Q    205824       // 2 x 4 x 528 = 4224
#define SB_G    210048       // 512
#define SB_B2   210560       // 1024
#define K3G_SMEM 211584

__global__ __launch_bounds__(512, 1) void k3g(const float* __restrict__ b2) {
    extern __shared__ char smem[];
    uint32_t sb = smem_u32(smem);
    int tid = threadIdx.x, lane = tid & 31, wid = tid >> 5;
    int mwarp = wid >> 2, nwarp = wid & 3;
    int e = blockIdx.x / 48, g = blockIdx.x % 48;
    int bt0, nbt;
    if (g < 16) { bt0 = g * 6; nbt = 6; }
    else        { bt0 = 96 + (g - 16) * 5; nbt = 5; }
    int t0 = bt0 * 8, ntiles = nbt * 8;

    float* g_s = (float*)(smem + SB_G);
    float* b2s = (float*)(smem + SB_B2);
    const __half* Pg = d_PQh + (size_t)(e * 2) * NNODE * 256;
    const __half* Qg = d_PQh + (size_t)(e * 2 + 1) * NNODE * 256;

    auto stageP = [&](int bt, int pb) {
        const __half* src = Pg + (size_t)bt * 32 * 256;
        for (int i = tid; i < 1024; i += 512) {
            int r = i >> 5, c = i & 31;
            CP_ASYNC16(sb + SB_P + (uint32_t)(pb * 16896 + r * 528 + c * 16),
                       (const char*)(src + r * 256 + c * 8));
        }
        CP_COMMIT();
    };
    auto stageQ = [&](int t, int qb) {
        int bt = t >> 3, a0 = (t & 7) * 4;
        const __half* src = Qg + (size_t)(bt * 32 + a0) * 256;
        if (tid < 128) {
            int r = tid >> 5, c = tid & 31;
            CP_ASYNC16(sb + SB_Q + (uint32_t)(qb * 2112 + r * 528 + c * 16),
                       (const char*)(src + r * 256 + c * 8));
        }
        CP_COMMIT();
    };
    auto stageG = [&](int t) {
        if (tid < 128) {
            int bt = t >> 3, a0 = (t & 7) * 4;
            int grp = tid >> 5, j = tid & 31;
            g_s[tid] = (j < 31)
                ? d_G[(size_t)e * NEDGE + bt * 992 + (a0 + grp) * 31 + j] : 0.f;
        }
    };
    auto cvt = [](uint32_t pa, uint32_t qa) -> uint32_t {
        __half2 h = __hadd2(*(__half2*)&pa, *(__half2*)&qa);
        __half2 s = __hmul2(h, __float2half2_rn(0.01f));
        __half2 r = __hmax2(h, s);
        return *(uint32_t*)&r;
    };
    auto buildA = [&](int t, int kc, int ab, int pb, int qb) {
        int m = tid >> 2, sub = tid & 3;
        int a0 = (t & 7) * 4;
        int mq = m >> 5, j = m & 31;
        int rec = a0 + mq;
        int send = (j < 31) ? (j + (j >= rec)) : 0;   // dummy rows gated to 0 later
        const uint4* P4 = (const uint4*)(smem + SB_P + pb * 16896 + send * 528
                                         + kc * 128 + sub * 32);
        const uint4* Q4 = (const uint4*)(smem + SB_Q + qb * 2112 + mq * 528
                                         + kc * 128 + sub * 32);
        uint4 p0 = P4[0], p1 = P4[1], q0 = Q4[0], q1 = Q4[1];
        uint4 o0, o1;
        o0.x = cvt(p0.x, q0.x); o0.y = cvt(p0.y, q0.y);
        o0.z = cvt(p0.z, q0.z); o0.w = cvt(p0.w, q0.w);
        o1.x = cvt(p1.x, q1.x); o1.y = cvt(p1.y, q1.y);
        o1.z = cvt(p1.z, q1.z); o1.w = cvt(p1.w, q1.w);
        uint4* dst = (uint4*)(smem + SB_A + ab * 18432 + m * 144 + sub * 32);
        dst[0] = o0; dst[1] = o1;
    };

    // ---- prologue: b2, full B, first P/Q ----
    if (tid < 256) b2s[tid] = b2[(e + 1) * 256 + tid];
    {
        const __half* Wsrc = d_Wh + (size_t)e * 65536;
        for (int i = tid; i < 8192; i += 512) {
            int n = i >> 5, c = i & 31;
            CP_ASYNC16(sb + SB_B + (uint32_t)(n * 528 + c * 16),
                       (const char*)(Wsrc + n * 256 + c * 8));
        }
        CP_COMMIT();
    }
    int pb = 0;
    stageP(bt0, 0);
    stageQ(t0, 0);
    CP_WAIT(0);
    __syncthreads();

    for (int ti = 0; ti < ntiles; ++ti) {
        int t = t0 + ti, qb = ti & 1;
        int bt = t >> 3, a0 = (t & 7) * 4;
        buildA(t, 0, 0, pb, qb);
        stageG(t);
        __syncthreads();

        float acc[2][8][4];
#pragma unroll
        for (int ms = 0; ms < 2; ++ms)
#pragma unroll
            for (int ns = 0; ns < 8; ++ns)
#pragma unroll
                for (int c = 0; c < 4; ++c) acc[ms][ns][c] = 0.f;

        for (int kc = 0; kc < 4; ++kc) {
            if (kc < 3) {
                buildA(t, kc + 1, (kc + 1) & 1, pb, qb);
            } else if (ti + 1 < ntiles) {
                stageQ(t + 1, qb ^ 1);
                if (((t + 1) & 7) == 0) stageP((t + 1) >> 3, pb ^ 1);
            }
            uint32_t a_l = sb + SB_A + (uint32_t)((kc & 1) * 18432)
                         + (uint32_t)(mwarp * 32 + (lane & 7) + ((lane >> 3) & 1) * 8) * 144u
                         + ((lane >> 4) & 1) * 16u;
            uint32_t b_l = sb + SB_B
                         + (uint32_t)(nwarp * 64 + (lane & 7) + ((lane >> 4) & 1) * 8) * 528u
                         + (uint32_t)(kc * 128) + ((lane >> 3) & 1) * 16u;
#pragma unroll
            for (int ks = 0; ks < 4; ++ks) {
                uint32_t af0[4], af1[4];
                LDSM_X4(af0, a_l + ks * 32);
                LDSM_X4(af1, a_l + 16 * 144 + ks * 32);
#pragma unroll
                for (int p = 0; p < 4; ++p) {
                    uint32_t bf[4];
                    LDSM_X4(bf, b_l + p * 8448 + ks * 32);
                    MMA16816(acc[0][2 * p],     af0, bf);
                    MMA16816(acc[0][2 * p + 1], af0, bf + 2);
                    MMA16816(acc[1][2 * p],     af1, bf);
                    MMA16816(acc[1][2 * p + 1], af1, bf + 2);
                }
            }
            if (kc == 3) {
                // epilogue: bias + lrelu + gate, reduce 32 rows (one receiver)/warp
                float g00 = g_s[mwarp * 32 + (lane >> 2)];
                float g01 = g_s[mwarp * 32 + (lane >> 2) + 8];
                float g10 = g_s[mwarp * 32 + 16 + (lane >> 2)];
                float g11 = g_s[mwarp * 32 + 24 + (lane >> 2)];
                int node = bt * 32 + a0 + mwarp;
#pragma unroll
                for (int nst = 0; nst < 8; ++nst) {
                    int c0 = nwarp * 64 + nst * 8 + (lane & 3) * 2;
                    float b0v = b2s[c0], b1v = b2s[c0 + 1];
                    float s0 = lrelu(acc[0][nst][0] + b0v) * g00 + lrelu(acc[0][nst][2] + b0v) * g01
                             + lrelu(acc[1][nst][0] + b0v) * g10 + lrelu(acc[1][nst][2] + b0v) * g11;
                    float s1 = lrelu(acc[0][nst][1] + b1v) * g00 + lrelu(acc[0][nst][3] + b1v) * g01
                             + lrelu(acc[1][nst][1] + b1v) * g10 + lrelu(acc[1][nst][3] + b1v) * g11;
                    s0 += __shfl_xor_sync(~0u, s0, 4);  s1 += __shfl_xor_sync(~0u, s1, 4);
                    s0 += __shfl_xor_sync(~0u, s0, 8);  s1 += __shfl_xor_sync(~0u, s1, 8);
                    s0 += __shfl_xor_sync(~0u, s0, 16); s1 += __shfl_xor_sync(~0u, s1, 16);
                    if (lane < 4) {
                        float* dst = d_AGGe + ((size_t)e * NNODE + node) * 256 + c0;
                        dst[0] = s0; dst[1] = s1;
                    }
                }
                if (ti + 1 < ntiles) CP_WAIT(0);
            }
            __syncthreads();
        }
        if (((t + 1) & 7) == 0) pb ^= 1;
    }
}

// ------------------------- k5: output MLP + residual -----------------------
__global__ __launch_bounds__(256) void k5(const float* __restrict__ fw1,
                                          const float* __restrict__ fb1,
                                          const float* __restrict__ fw2,
                                          const float* __restrict__ fb2,
                                          const float* __restrict__ fw3,
                                          const float* __restrict__ fb3,
                                          float* __restrict__ out) {
    __shared__ float aug[16][320];
    __shared__ float hbuf[16][256];
    int row0 = blockIdx.x * 16, tid = threadIdx.x;
    for (int i = tid; i < 16 * 64; i += 256) aug[i >> 6][i & 63] = d_X[row0 * 64 + i];
    for (int i = tid; i < 16 * 256; i += 256) {
        size_t base = (size_t)row0 * 256 + i;
        aug[i >> 8][64 + (i & 255)] = d_AGGe[base]
                                    + d_AGGe[(size_t)NNODE * 256 + base]
                                    + d_AGGe[(size_t)2 * NNODE * 256 + base];
    }
    __syncthreads();
    {
        float acc[16];
#pragma unroll
        for (int m = 0; m < 16; ++m) acc[m] = 0.f;
#pragma unroll 4
        for (int k = 0; k < 320; ++k) {
            float w = fw1[k * 256 + tid];
#pragma unroll
            for (int m = 0; m < 16; ++m) acc[m] += aug[m][k] * w;
        }
        float b = fb1[tid];
#pragma unroll
        for (int m = 0; m < 16; ++m) hbuf[m][tid] = lrelu(acc[m] + b);
    }
    __syncthreads();
    {
        float acc[16];
#pragma unroll
        for (int m = 0; m < 16; ++m) acc[m] = 0.f;
#pragma unroll 4
        for (int k = 0; k < 256; ++k) {
            float w = fw2[k * 256 + tid];
#pragma unroll
            for (int m = 0; m < 16; ++m) acc[m] += hbuf[m][k] * w;
        }
        float b = fb2[tid];
#pragma unroll
        for (int m = 0; m < 16; ++m) aug[m][tid] = lrelu(acc[m] + b);
    }
    __syncthreads();
    {
        int c = tid & 63, sub = tid >> 6;
        float acc3[4] = {0.f, 0.f, 0.f, 0.f};
#pragma unroll 4
        for (int k = 0; k < 256; ++k) {
            float w = fw3[k * 64 + c];
#pragma unroll
            for (int mm = 0; mm < 4; ++mm) acc3[mm] += aug[sub * 4 + mm][k] * w;
        }
        float b = fb3[c];
#pragma unroll
        for (int mm = 0; mm < 4; ++mm) {
            int n = row0 + sub * 4 + mm;
            int bb = n >> 11, t = (n >> 5) & 63, a = n & 31;
            if (t < 63)
                out[(((bb * 32 + a) * 63) + t) * 64 + c] = d_X[n * 64 + c] + acc3[mm] + b;
        }
    }
}

// ---------------------------------------------------------------------------
extern "C" void kernel_launch(void* const* d_in, const int* in_sizes, int n_in,
                              void* d_out, int out_size) {
    (void)in_sizes; (void)n_in; (void)out_size;
    const float* inputs    = (const float*)d_in[0];
    const float* state     = (const float*)d_in[1];
    const float* rel_type  = (const float*)d_in[2];
    const float* msg_fc1_w = (const float*)d_in[5];
    const float* msg_fc1_b = (const float*)d_in[6];
    const float* msg_fc2_w = (const float*)d_in[7];
    const float* msg_fc2_b = (const float*)d_in[8];
    const float* out_fc1_w = (const float*)d_in[9];
    const float* out_fc1_b = (const float*)d_in[10];
    const float* out_fc2_w = (const float*)d_in[11];
    const float* out_fc2_b = (const float*)d_in[12];
    const float* out_fc3_w = (const float*)d_in[13];
    const float* out_fc3_b = (const float*)d_in[14];
    float* out = (float*)d_out;

    k1x<<<(NNODE * 16 + 255) / 256, 256>>>((const float4*)inputs);
    k1g<<<(NEDGE + 255) / 256, 256>>>(state, (const float4*)rel_type);
    k2<<<NNODE / 32, 256>>>(msg_fc1_w, msg_fc1_b);
    k2w<<<dim3(8, 8, 3), dim3(32, 8)>>>(msg_fc2_w);

    cudaFuncSetAttribute(k3g, cudaFuncAttributeMaxDynamicSharedMemorySize, K3G_SMEM);
    k3g<<<144, 512, K3G_SMEM>>>(msg_fc2_b);

    k5<<<NNODE / 16, 256>>>(out_fc1_w, out_fc1_b, out_fc2_w, out_fc2_b,
                            out_fc3_w, out_fc3_b, out);
}

// round 9
// speedup vs baseline: 3.5235x; 1.0509x over previous
#include <cuda_runtime.h>
#include <cuda_fp16.h>
#include <cstdint>

#define NNODE 8192
#define NEDGE 253952
#define NBT   256

__device__ float  d_X  [NNODE * 64];
__device__ __half d_PQh[6 * NNODE * 256];      // [e*2+half][node][256] fp16
__device__ float  d_G  [3 * NEDGE];
__device__ float  d_AGGe[3 * NNODE * 256];     // per-expert partial agg
__device__ __half d_Wh[3 * 256 * 256];         // [e][n][k] fp16

__device__ __forceinline__ float lrelu(float v) { return fmaxf(v, 0.01f * v); }

__device__ __forceinline__ uint32_t smem_u32(const void* p) {
    uint32_t a;
    asm("{ .reg .u64 t; cvta.to.shared.u64 t, %1; cvt.u32.u64 %0, t; }" : "=r"(a) : "l"(p));
    return a;
}

#define CP_ASYNC16(dst, src) \
    asm volatile("cp.async.cg.shared.global [%0], [%1], 16;" :: "r"(dst), "l"(src) : "memory")
#define CP_COMMIT() asm volatile("cp.async.commit_group;" ::: "memory")
#define CP_WAIT(n)  asm volatile("cp.async.wait_group %0;" :: "n"(n) : "memory")

#define LDSM_X4(r, a) \
    asm volatile("ldmatrix.sync.aligned.m8n8.x4.shared.b16 {%0,%1,%2,%3}, [%4];" \
        : "=r"((r)[0]), "=r"((r)[1]), "=r"((r)[2]), "=r"((r)[3]) : "r"(a))
#define MMA16816(d, a, b) \
    asm volatile("mma.sync.aligned.m16n8k16.row.col.f32.f16.f16.f32 " \
        "{%0,%1,%2,%3}, {%4,%5,%6,%7}, {%8,%9}, {%0,%1,%2,%3};" \
        : "+f"((d)[0]), "+f"((d)[1]), "+f"((d)[2]), "+f"((d)[3]) \
        : "r"((a)[0]), "r"((a)[1]), "r"((a)[2]), "r"((a)[3]), "r"((b)[0]), "r"((b)[1]))

// ------------------------- k1x / k1g -------------------------------------
__global__ void k1x(const float4* __restrict__ in4) {
    int idx = blockIdx.x * blockDim.x + threadIdx.x;
    if (idx >= NNODE * 16) return;
    int n = idx >> 4, q = idx & 15;
    int b = n >> 11, t = (n >> 5) & 63, a = n & 31;
    ((float4*)d_X)[idx] = in4[(((b * 32 + a) * 64) + t) * 16 + q];
}

__global__ void k1g(const float* __restrict__ state, const float4* __restrict__ rt4) {
    int idx = blockIdx.x * blockDim.x + threadIdx.x;
    if (idx >= NEDGE) return;
    int bt = idx / 992, r = idx - bt * 992;
    int b = bt >> 6, t = bt & 63;
    int rec = r / 31, j = r - rec * 31;
    int send = j + (j >= rec);
    const float4 st = *(const float4*)&state[(((b * 32 + send) * 64) + t) * 4];
    const float4* rt = rt4 + (b * 992 + r) * 4;
    float4 r0 = rt[0], r1 = rt[1], r2 = rt[2], r3 = rt[3];
    d_G[0 * NEDGE + idx] = st.x * r0.y + st.y * r1.y + st.z * r2.y + st.w * r3.y;
    d_G[1 * NEDGE + idx] = st.x * r0.z + st.y * r1.z + st.z * r2.z + st.w * r3.z;
    d_G[2 * NEDGE + idx] = st.x * r0.w + st.y * r1.w + st.z * r2.w + st.w * r3.w;
}

// ------------------------- k2: P/Q node GEMMs -> fp16 (64-row blocks) ------
__global__ __launch_bounds__(256) void k2(const float* __restrict__ w1,
                                          const float* __restrict__ b1) {
    __shared__ float xs[64][64];
    int row0 = blockIdx.x * 64, tid = threadIdx.x;
    for (int i = tid; i < 64 * 64; i += 256) xs[i >> 6][i & 63] = d_X[row0 * 64 + i];
    __syncthreads();
    for (int chunk = 0; chunk < 6; ++chunk) {
        int e = chunk >> 1, half = chunk & 1;
        const float* W = w1 + ((size_t)((e + 1) * 128 + half * 64)) * 256;
        float acc[64];
#pragma unroll
        for (int m = 0; m < 64; ++m) acc[m] = 0.f;
#pragma unroll 2
        for (int k = 0; k < 64; ++k) {
            float w = W[k * 256 + tid];
#pragma unroll
            for (int m = 0; m < 64; ++m) acc[m] += xs[m][k] * w;
        }
        float bias = (half == 0) ? b1[(e + 1) * 256 + tid] : 0.f;
        __half* dst = d_PQh + ((size_t)chunk * NNODE + row0) * 256 + tid;
#pragma unroll
        for (int m = 0; m < 64; ++m) dst[m * 256] = __float2half(acc[m] + bias);
    }
}

// --------------- k2w: W2 transpose -> fp16 [e][n][k] -----------------------
__global__ void k2w(const float* __restrict__ w2) {
    __shared__ float tile[32][33];
    int e = blockIdx.z, kt = blockIdx.x * 32, nt = blockIdx.y * 32;
    int tx = threadIdx.x, ty = threadIdx.y;          // 32 x 8
#pragma unroll
    for (int r = 0; r < 4; ++r)
        tile[ty + r * 8][tx] = w2[((size_t)(e + 1) * 256 + kt + ty + r * 8) * 256 + nt + tx];
    __syncthreads();
#pragma unroll
    for (int r = 0; r < 4; ++r) {
        int n = nt + ty + r * 8;
        d_Wh[((size_t)e * 256 + n) * 256 + kt + tx] = __float2half(tile[tx][ty + r * 8]);
    }
}

// ------------------------- k3g: B-resident fp16 HMMA edge GEMM -------------
// Grid = 3 experts x 48 blocks. Per expert: 2048 quad-tiles split 43/42 per
// block (quad-granular balance). B (256x256 fp16) resident in SMEM.
#define SB_B    0            // 256 x 528 = 135168
#define SB_A    135168       // 2 x 128 x 144 = 36864
#define SB_P    172032       // 2 x 32 x 528 = 33792
#define SB_Q    205824       // 2 x 4 x 528 = 4224
#define SB_G    210048       // 512
#define SB_B2   210560       // 1024
#define K3G_SMEM 211584

__global__ __launch_bounds__(512, 1) void k3g(const float* __restrict__ b2) {
    extern __shared__ char smem[];
    uint32_t sb = smem_u32(smem);
    int tid = threadIdx.x, lane = tid & 31, wid = tid >> 5;
    int mwarp = wid >> 2, nwarp = wid & 3;
    int e = blockIdx.x / 48, j = blockIdx.x % 48;
    int t0     = (j < 32) ? j * 43 : 32 * 43 + (j - 32) * 42;
    int ntiles = (j < 32) ? 43 : 42;

    float* g_s = (float*)(smem + SB_G);
    float* b2s = (float*)(smem + SB_B2);
    const __half* Pg = d_PQh + (size_t)(e * 2) * NNODE * 256;
    const __half* Qg = d_PQh + (size_t)(e * 2 + 1) * NNODE * 256;

    auto stageP = [&](int bt, int pb) {
        const __half* src = Pg + (size_t)bt * 32 * 256;
        for (int i = tid; i < 1024; i += 512) {
            int r = i >> 5, c = i & 31;
            CP_ASYNC16(sb + SB_P + (uint32_t)(pb * 16896 + r * 528 + c * 16),
                       (const char*)(src + r * 256 + c * 8));
        }
        CP_COMMIT();
    };
    auto stageQ = [&](int t, int qb) {
        int bt = t >> 3, a0 = (t & 7) * 4;
        const __half* src = Qg + (size_t)(bt * 32 + a0) * 256;
        if (tid < 128) {
            int r = tid >> 5, c = tid & 31;
            CP_ASYNC16(sb + SB_Q + (uint32_t)(qb * 2112 + r * 528 + c * 16),
                       (const char*)(src + r * 256 + c * 8));
        }
        CP_COMMIT();
    };
    auto stageG = [&](int t) {
        if (tid < 128) {
            int bt = t >> 3, a0 = (t & 7) * 4;
            int grp = tid >> 5, jj = tid & 31;
            g_s[tid] = (jj < 31)
                ? d_G[(size_t)e * NEDGE + bt * 992 + (a0 + grp) * 31 + jj] : 0.f;
        }
    };
    auto cvt = [](uint32_t pa, uint32_t qa) -> uint32_t {
        __half2 h = __hadd2(*(__half2*)&pa, *(__half2*)&qa);
        __half2 s = __hmul2(h, __float2half2_rn(0.01f));
        __half2 r = __hmax2(h, s);
        return *(uint32_t*)&r;
    };
    auto buildA = [&](int t, int kc, int ab, int pb, int qb) {
        int m = tid >> 2, sub = tid & 3;
        int a0 = (t & 7) * 4;
        int mq = m >> 5, jj = m & 31;
        int rec = a0 + mq;
        int send = (jj < 31) ? (jj + (jj >= rec)) : 0;   // dummy rows gated later
        const uint4* P4 = (const uint4*)(smem + SB_P + pb * 16896 + send * 528
                                         + kc * 128 + sub * 32);
        const uint4* Q4 = (const uint4*)(smem + SB_Q + qb * 2112 + mq * 528
                                         + kc * 128 + sub * 32);
        uint4 p0 = P4[0], p1 = P4[1], q0 = Q4[0], q1 = Q4[1];
        uint4 o0, o1;
        o0.x = cvt(p0.x, q0.x); o0.y = cvt(p0.y, q0.y);
        o0.z = cvt(p0.z, q0.z); o0.w = cvt(p0.w, q0.w);
        o1.x = cvt(p1.x, q1.x); o1.y = cvt(p1.y, q1.y);
        o1.z = cvt(p1.z, q1.z); o1.w = cvt(p1.w, q1.w);
        uint4* dst = (uint4*)(smem + SB_A + ab * 18432 + m * 144 + sub * 32);
        dst[0] = o0; dst[1] = o1;
    };

    // ---- prologue: b2, full B, first P/Q ----
    if (tid < 256) b2s[tid] = b2[(e + 1) * 256 + tid];
    {
        const __half* Wsrc = d_Wh + (size_t)e * 65536;
        for (int i = tid; i < 8192; i += 512) {
            int n = i >> 5, c = i & 31;
            CP_ASYNC16(sb + SB_B + (uint32_t)(n * 528 + c * 16),
                       (const char*)(Wsrc + n * 256 + c * 8));
        }
        CP_COMMIT();
    }
    int pb = 0;
    stageP(t0 >> 3, 0);
    stageQ(t0, 0);
    CP_WAIT(0);
    __syncthreads();

    for (int ti = 0; ti < ntiles; ++ti) {
        int t = t0 + ti, qb = ti & 1;
        int bt = t >> 3, a0 = (t & 7) * 4;
        buildA(t, 0, 0, pb, qb);
        stageG(t);
        __syncthreads();

        float acc[2][8][4];
#pragma unroll
        for (int ms = 0; ms < 2; ++ms)
#pragma unroll
            for (int ns = 0; ns < 8; ++ns)
#pragma unroll
                for (int c = 0; c < 4; ++c) acc[ms][ns][c] = 0.f;

        for (int kc = 0; kc < 4; ++kc) {
            if (kc < 3) {
                buildA(t, kc + 1, (kc + 1) & 1, pb, qb);
            } else if (ti + 1 < ntiles) {
                stageQ(t + 1, qb ^ 1);
                if (((t + 1) & 7) == 0) stageP((t + 1) >> 3, pb ^ 1);
            }
            uint32_t a_l = sb + SB_A + (uint32_t)((kc & 1) * 18432)
                         + (uint32_t)(mwarp * 32 + (lane & 7) + ((lane >> 3) & 1) * 8) * 144u
                         + ((lane >> 4) & 1) * 16u;
            uint32_t b_l = sb + SB_B
                         + (uint32_t)(nwarp * 64 + (lane & 7) + ((lane >> 4) & 1) * 8) * 528u
                         + (uint32_t)(kc * 128) + ((lane >> 3) & 1) * 16u;
#pragma unroll
            for (int ks = 0; ks < 4; ++ks) {
                uint32_t af0[4], af1[4];
                LDSM_X4(af0, a_l + ks * 32);
                LDSM_X4(af1, a_l + 16 * 144 + ks * 32);
#pragma unroll
                for (int p = 0; p < 4; ++p) {
                    uint32_t bf[4];
                    LDSM_X4(bf, b_l + p * 8448 + ks * 32);
                    MMA16816(acc[0][2 * p],     af0, bf);
                    MMA16816(acc[0][2 * p + 1], af0, bf + 2);
                    MMA16816(acc[1][2 * p],     af1, bf);
                    MMA16816(acc[1][2 * p + 1], af1, bf + 2);
                }
            }
            if (kc == 3) {
                float g00 = g_s[mwarp * 32 + (lane >> 2)];
                float g01 = g_s[mwarp * 32 + (lane >> 2) + 8];
                float g10 = g_s[mwarp * 32 + 16 + (lane >> 2)];
                float g11 = g_s[mwarp * 32 + 24 + (lane >> 2)];
                int node = bt * 32 + a0 + mwarp;
#pragma unroll
                for (int nst = 0; nst < 8; ++nst) {
                    int c0 = nwarp * 64 + nst * 8 + (lane & 3) * 2;
                    float b0v = b2s[c0], b1v = b2s[c0 + 1];
                    float s0 = lrelu(acc[0][nst][0] + b0v) * g00 + lrelu(acc[0][nst][2] + b0v) * g01
                             + lrelu(acc[1][nst][0] + b0v) * g10 + lrelu(acc[1][nst][2] + b0v) * g11;
                    float s1 = lrelu(acc[0][nst][1] + b1v) * g00 + lrelu(acc[0][nst][3] + b1v) * g01
                             + lrelu(acc[1][nst][1] + b1v) * g10 + lrelu(acc[1][nst][3] + b1v) * g11;
                    s0 += __shfl_xor_sync(~0u, s0, 4);  s1 += __shfl_xor_sync(~0u, s1, 4);
                    s0 += __shfl_xor_sync(~0u, s0, 8);  s1 += __shfl_xor_sync(~0u, s1, 8);
                    s0 += __shfl_xor_sync(~0u, s0, 16); s1 += __shfl_xor_sync(~0u, s1, 16);
                    if (lane < 4) {
                        float* dst = d_AGGe + ((size_t)e * NNODE + node) * 256 + c0;
                        dst[0] = s0; dst[1] = s1;
                    }
                }
                if (ti + 1 < ntiles) CP_WAIT(0);
            }
            __syncthreads();
        }
        if (((t + 1) & 7) == 0) pb ^= 1;
    }
}

// --------------- k5: output MLP + residual (64-row blocks) -----------------
#define K5_SMEM (64 * 320 * 4 + 64 * 256 * 4)   // aug + hbuf = 147456

__global__ __launch_bounds__(256) void k5(const float* __restrict__ fw1,
                                          const float* __restrict__ fb1,
                                          const float* __restrict__ fw2,
                                          const float* __restrict__ fb2,
                                          const float* __restrict__ fw3,
                                          const float* __restrict__ fb3,
                                          float* __restrict__ out) {
    extern __shared__ float sm5[];
    float* aug  = sm5;               // [64][320]
    float* hbuf = sm5 + 64 * 320;    // [64][256]
    int row0 = blockIdx.x * 64, tid = threadIdx.x;

    for (int i = tid; i < 64 * 64; i += 256)
        aug[(i >> 6) * 320 + (i & 63)] = d_X[row0 * 64 + i];
    for (int i = tid; i < 64 * 256; i += 256) {
        size_t base = (size_t)row0 * 256 + i;
        aug[(i >> 8) * 320 + 64 + (i & 255)] = d_AGGe[base]
                                             + d_AGGe[(size_t)NNODE * 256 + base]
                                             + d_AGGe[(size_t)2 * NNODE * 256 + base];
    }
    __syncthreads();

    // layer 1: 320 -> 256
    {
        float acc[64];
#pragma unroll
        for (int m = 0; m < 64; ++m) acc[m] = 0.f;
#pragma unroll 2
        for (int k = 0; k < 320; ++k) {
            float w = fw1[k * 256 + tid];
#pragma unroll
            for (int m = 0; m < 64; ++m) acc[m] += aug[m * 320 + k] * w;
        }
        float b = fb1[tid];
#pragma unroll
        for (int m = 0; m < 64; ++m) hbuf[m * 256 + tid] = lrelu(acc[m] + b);
    }
    __syncthreads();

    // layer 2: 256 -> 256 (into aug cols 0..255)
    {
        float acc[64];
#pragma unroll
        for (int m = 0; m < 64; ++m) acc[m] = 0.f;
#pragma unroll 2
        for (int k = 0; k < 256; ++k) {
            float w = fw2[k * 256 + tid];
#pragma unroll
            for (int m = 0; m < 64; ++m) acc[m] += hbuf[m * 256 + k] * w;
        }
        float b = fb2[tid];
#pragma unroll
        for (int m = 0; m < 64; ++m) aug[m * 320 + tid] = lrelu(acc[m] + b);
    }
    __syncthreads();

    // layer 3: 256 -> 64, residual, write (skip t = 63)
    {
        int c = tid & 63, sub = tid >> 6;       // 4 subs x 16 rows
        float acc3[16];
#pragma unroll
        for (int mm = 0; mm < 16; ++mm) acc3[mm] = 0.f;
#pragma unroll 2
        for (int k = 0; k < 256; ++k) {
            float w = fw3[k * 64 + c];
#pragma unroll
            for (int mm = 0; mm < 16; ++mm)
                acc3[mm] += aug[(sub * 16 + mm) * 320 + k] * w;
        }
        float b = fb3[c];
#pragma unroll
        for (int mm = 0; mm < 16; ++mm) {
            int n = row0 + sub * 16 + mm;
            int bb = n >> 11, t = (n >> 5) & 63, a = n & 31;
            if (t < 63)
                out[(((bb * 32 + a) * 63) + t) * 64 + c] = d_X[n * 64 + c] + acc3[mm] + b;
        }
    }
}

// ---------------------------------------------------------------------------
extern "C" void kernel_launch(void* const* d_in, const int* in_sizes, int n_in,
                              void* d_out, int out_size) {
    (void)in_sizes; (void)n_in; (void)out_size;
    const float* inputs    = (const float*)d_in[0];
    const float* state     = (const float*)d_in[1];
    const float* rel_type  = (const float*)d_in[2];
    const float* msg_fc1_w = (const float*)d_in[5];
    const float* msg_fc1_b = (const float*)d_in[6];
    const float* msg_fc2_w = (const float*)d_in[7];
    const float* msg_fc2_b = (const float*)d_in[8];
    const float* out_fc1_w = (const float*)d_in[9];
    const float* out_fc1_b = (const float*)d_in[10];
    const float* out_fc2_w = (const float*)d_in[11];
    const float* out_fc2_b = (const float*)d_in[12];
    const float* out_fc3_w = (const float*)d_in[13];
    const float* out_fc3_b = (const float*)d_in[14];
    float* out = (float*)d_out;

    k1x<<<(NNODE * 16 + 255) / 256, 256>>>((const float4*)inputs);
    k1g<<<(NEDGE + 255) / 256, 256>>>(state, (const float4*)rel_type);
    k2<<<NNODE / 64, 256>>>(msg_fc1_w, msg_fc1_b);
    k2w<<<dim3(8, 8, 3), dim3(32, 8)>>>(msg_fc2_w);

    cudaFuncSetAttribute(k3g, cudaFuncAttributeMaxDynamicSharedMemorySize, K3G_SMEM);
    k3g<<<144, 512, K3G_SMEM>>>(msg_fc2_b);

    cudaFuncSetAttribute(k5, cudaFuncAttributeMaxDynamicSharedMemorySize, K5_SMEM);
    k5<<<NNODE / 64, 256, K5_SMEM>>>(out_fc1_w, out_fc1_b, out_fc2_w, out_fc2_b,
                                     out_fc3_w, out_fc3_b, out);
}